// round 9
// baseline (speedup 1.0000x reference)
#include <cuda_runtime.h>
#include <cuda_fp16.h>
#include <cstdint>

#define DINLINE __device__ __forceinline__

static constexpr int BATCH = 65536;
static constexpr int HDIM  = 256;
static constexpr int COMB  = 512;
static constexpr int MT    = 128;     // CTA M tile
static constexpr int NT    = 128;     // CTA N tile (= 32 h-cols x 4 gates)
static constexpr int KCH   = 64;      // K chunk
static constexpr int NCHUNK = COMB / KCH;   // 8
static constexpr int NSTAGE = 3;
static constexpr int NSET  = 4;       // fp16 accumulator K-split sets (2 chunks each)

static constexpr int SA = 72;                       // smem row stride in halves (144B)
static constexpr uint32_t A_TILE_B = MT * SA * 2;   // 18432
static constexpr uint32_t STAGE_B  = 2 * A_TILE_B;  // 36864 (A then W)
static constexpr uint32_t SMEM_PIPE = NSTAGE * STAGE_B;  // 110592
static constexpr int GS = 136;                      // gate smem stride (floats)

// ---- fp16 scratch (static device arrays; no allocation) ----
__device__ __half g_A16[(size_t)BATCH * COMB];      // concat(x,h) fp16
__device__ __half g_Wp[(size_t)4 * HDIM * COMB];    // packed: row n = hcol*4+gate

// ============================ PTX helpers ============================
DINLINE uint32_t smem_u32(const void* p) {
    uint32_t a;
    asm("{ .reg .u64 t; cvta.to.shared.u64 t, %1; cvt.u32.u64 %0, t; }" : "=r"(a) : "l"(p));
    return a;
}
DINLINE void cp_async16(uint32_t dst, const void* src) {
    asm volatile("cp.async.cg.shared.global [%0], [%1], 16;" :: "r"(dst), "l"(src));
}
DINLINE void cp_commit() { asm volatile("cp.async.commit_group;" ::: "memory"); }
template <int N> DINLINE void cp_wait() {
    asm volatile("cp.async.wait_group %0;" :: "n"(N) : "memory");
}
DINLINE void ldsm_x4(uint32_t (&r)[4], uint32_t addr) {
    asm volatile("ldmatrix.sync.aligned.m8n8.x4.shared.b16 {%0,%1,%2,%3}, [%4];"
                 : "=r"(r[0]), "=r"(r[1]), "=r"(r[2]), "=r"(r[3]) : "r"(addr));
}
// fp16-accumulate variant: D/C are 2 b32 regs (4 halves)
DINLINE void mma16816_f16(uint32_t (&d)[2], const uint32_t (&a)[4], const uint32_t* b) {
    asm volatile(
        "mma.sync.aligned.m16n8k16.row.col.f16.f16.f16.f16 "
        "{%0,%1}, {%2,%3,%4,%5}, {%6,%7}, {%0,%1};"
        : "+r"(d[0]), "+r"(d[1])
        : "r"(a[0]), "r"(a[1]), "r"(a[2]), "r"(a[3]), "r"(b[0]), "r"(b[1]));
}
DINLINE float2 h2f(uint32_t u) {
    union { uint32_t u; __half2 h; } c;
    c.u = u;
    return __half22float2(c.h);
}

// ============================ math helpers ============================
DINLINE float fast_sigmoid(float x) { return __fdividef(1.0f, 1.0f + __expf(-x)); }
DINLINE float fast_tanh(float x) {
    float ax = fabsf(x);
    float e  = __expf(-2.0f * ax);
    float r  = __fdividef(1.0f - e, 1.0f + e);
    return copysignf(r, x);
}

// ============================ prepass kernels ============================
__global__ void __launch_bounds__(256) convert_a_kernel(
    const float* __restrict__ x, const float* __restrict__ h) {
    size_t g  = (size_t)blockIdx.x * 256 + threadIdx.x;
    int m  = (int)(g >> 6);
    int k0 = ((int)g & 63) * 8;
    const float* src = (k0 < 256) ? (x + (size_t)m * 256 + k0)
                                  : (h + (size_t)m * 256 + (k0 - 256));
    float4 a = __ldg((const float4*)src);
    float4 b = __ldg((const float4*)src + 1);
    union { uint4 u; __half2 hh[4]; } pk;
    pk.hh[0] = __floats2half2_rn(a.x, a.y);
    pk.hh[1] = __floats2half2_rn(a.z, a.w);
    pk.hh[2] = __floats2half2_rn(b.x, b.y);
    pk.hh[3] = __floats2half2_rn(b.z, b.w);
    *reinterpret_cast<uint4*>(g_A16 + (size_t)m * COMB + k0) = pk.u;
}

__global__ void __launch_bounds__(256) convert_w_kernel(
    const float* __restrict__ Wf, const float* __restrict__ Wi,
    const float* __restrict__ Wo, const float* __restrict__ Wg) {
    int g  = blockIdx.x * 256 + threadIdx.x;
    int r  = g >> 6;
    int k0 = (g & 63) * 8;
    int gate = r & 3;
    int hcol = r >> 2;
    const float* W = (gate == 0) ? Wf : (gate == 1) ? Wi : (gate == 2) ? Wo : Wg;
    const float* src = W + (size_t)hcol * COMB + k0;
    float4 a = __ldg((const float4*)src);
    float4 b = __ldg((const float4*)src + 1);
    union { uint4 u; __half2 hh2[4]; } pk;
    pk.hh2[0] = __floats2half2_rn(a.x, a.y);
    pk.hh2[1] = __floats2half2_rn(a.z, a.w);
    pk.hh2[2] = __floats2half2_rn(b.x, b.y);
    pk.hh2[3] = __floats2half2_rn(b.z, b.w);
    *reinterpret_cast<uint4*>(g_Wp + (size_t)r * COMB + k0) = pk.u;
}

// ============================ main fused GEMM+LSTM kernel ============================
// grid (8, 512): blockIdx.x = by (h-col block of 32), blockIdx.y = M tile.
// 256 threads, 8 warps: warp_m = wid&3 (32 rows), warp_n = wid>>2 (64 cols).
DINLINE void load_stage(uint32_t stb, const __half* gA, const __half* gW,
                        int kc, int t) {
    #pragma unroll
    for (int i = 0; i < 4; i++) {
        int idx = t + i * 256;           // 0..1023
        int m = idx >> 3, c = idx & 7;
        cp_async16(stb + (uint32_t)(m * SA + c * 8) * 2,
                   gA + (size_t)m * COMB + kc + c * 8);
    }
    #pragma unroll
    for (int i = 0; i < 4; i++) {
        int idx = t + i * 256;
        int n = idx >> 3, c = idx & 7;
        cp_async16(stb + A_TILE_B + (uint32_t)(n * SA + c * 8) * 2,
                   gW + (size_t)n * COMB + kc + c * 8);
    }
}

__global__ void __launch_bounds__(256, 1) lstm_gemm_kernel(
    const float* __restrict__ c_prev,
    const float* __restrict__ b_f, const float* __restrict__ b_i,
    const float* __restrict__ b_o, const float* __restrict__ b_g,
    float* __restrict__ out) {
    extern __shared__ char smem[];
    const uint32_t sbase = smem_u32(smem);
    float* gsm = (float*)smem;

    const int t    = threadIdx.x;
    const int lane = t & 31;
    const int wid  = t >> 5;
    const int warp_m = wid & 3;          // 4 M-warps (32 rows each)
    const int warp_n = wid >> 2;         // 2 N-warps (64 cols each)
    const int by = blockIdx.x;
    const int m0 = blockIdx.y * MT;

    const __half* gA = g_A16 + (size_t)m0 * COMB;
    const __half* gW = g_Wp + (size_t)by * NT * COMB;

    // ldmatrix per-lane address components
    const int A_row = (lane & 7) + ((lane >> 3) & 1) * 8;
    const int A_k   = (lane >> 4) * 8;
    const int B_n   = (lane & 7) + ((lane >> 3) >> 1) * 8;
    const int B_k   = ((lane >> 3) & 1) * 8;

    // fp16 accumulators: 4 K-split sets, each [2 m-tiles][8 n-tiles][2 regs]
    uint32_t hacc[NSET][2][8][2];
    #pragma unroll
    for (int s = 0; s < NSET; s++)
        #pragma unroll
        for (int i = 0; i < 2; i++)
            #pragma unroll
            for (int j = 0; j < 8; j++) {
                hacc[s][i][j][0] = 0u;
                hacc[s][i][j][1] = 0u;
            }

    #pragma unroll
    for (int s = 0; s < 2; s++) {
        load_stage(sbase + s * STAGE_B, gA, gW, s * KCH, t);
        cp_commit();
    }

    for (int k = 0; k < NCHUNK; k++) {
        if (k < NCHUNK - 1) cp_wait<1>();
        else                cp_wait<0>();
        __syncthreads();

        if (k + 2 < NCHUNK) {
            int sl = (k + 2) % NSTAGE;
            load_stage(sbase + sl * STAGE_B, gA, gW, (k + 2) * KCH, t);
            cp_commit();
        }

        const int kset = k >> 1;         // 2 chunks (K=128) per fp16 set
        const uint32_t stb = sbase + (k % NSTAGE) * STAGE_B;
        #pragma unroll
        for (int ks = 0; ks < 4; ks++) {
            uint32_t af[2][4];
            #pragma unroll
            for (int i = 0; i < 2; i++) {
                uint32_t addr = stb +
                    (uint32_t)((warp_m * 32 + i * 16 + A_row) * SA + ks * 16 + A_k) * 2;
                ldsm_x4(af[i], addr);
            }
            uint32_t bf[8][2];
            #pragma unroll
            for (int jj = 0; jj < 4; jj++) {
                uint32_t r[4];
                uint32_t addr = stb + A_TILE_B +
                    (uint32_t)((warp_n * 64 + jj * 16 + B_n) * SA + ks * 16 + B_k) * 2;
                ldsm_x4(r, addr);
                bf[jj * 2][0] = r[0]; bf[jj * 2][1] = r[1];
                bf[jj * 2 + 1][0] = r[2]; bf[jj * 2 + 1][1] = r[3];
            }
            #pragma unroll
            for (int i = 0; i < 2; i++)
                #pragma unroll
                for (int j = 0; j < 8; j++)
                    mma16816_f16(hacc[kset][i][j], af[i], bf[j]);
        }
    }

    // ---- sum the 4 fp16 sets in fp32, stage raw gate values to smem ----
    __syncthreads();
    {
        const int g = lane >> 2, tig = lane & 3;
        #pragma unroll
        for (int i = 0; i < 2; i++) {
            #pragma unroll
            for (int j = 0; j < 8; j++) {
                float2 lo = h2f(hacc[0][i][j][0]);
                float2 hi = h2f(hacc[0][i][j][1]);
                #pragma unroll
                for (int s = 1; s < NSET; s++) {
                    float2 l = h2f(hacc[s][i][j][0]);
                    float2 h = h2f(hacc[s][i][j][1]);
                    lo.x += l.x; lo.y += l.y;
                    hi.x += h.x; hi.y += h.y;
                }
                int r0 = warp_m * 32 + i * 16 + g;
                int n0 = warp_n * 64 + j * 8 + tig * 2;
                *(float2*)(gsm + r0 * GS + n0)       = lo;
                *(float2*)(gsm + (r0 + 8) * GS + n0) = hi;
            }
        }
    }
    __syncthreads();

    // ---- activation epilogue: fully coalesced ----
    const int hc   = t & 31;           // h-col within block
    const int rblk = t >> 5;           // 0..7
    const int hcol = by * 32 + hc;
    const float bF = __ldg(b_f + hcol), bI = __ldg(b_i + hcol);
    const float bO = __ldg(b_o + hcol), bG = __ldg(b_g + hcol);
    const size_t RBH = (size_t)BATCH * HDIM;

    #pragma unroll
    for (int it = 0; it < 16; it++) {
        int row = it * 8 + rblk;
        float4 gv = *(float4*)(gsm + row * GS + hc * 4);  // (f,i,o,g)
        size_t idx = (size_t)(m0 + row) * HDIM + hcol;
        float cp = __ldg(c_prev + idx);
        float f = fast_sigmoid(gv.x + bF);
        float i = fast_sigmoid(gv.y + bI);
        float o = fast_sigmoid(gv.z + bO);
        float g = fast_tanh(gv.w + bG);
        float c = f * cp + i * g;
        float h = o * fast_tanh(c);
        out[idx]           = h;
        out[RBH + idx]     = c;
        out[2 * RBH + idx] = f;
        out[3 * RBH + idx] = i;
        out[4 * RBH + idx] = o;
        out[5 * RBH + idx] = g;
    }
}

// ============================ host launch ============================
extern "C" void kernel_launch(void* const* d_in, const int* in_sizes, int n_in,
                              void* d_out, int out_size) {
    const float* x_t    = (const float*)d_in[0];
    const float* h_prev = (const float*)d_in[1];
    const float* c_prev = (const float*)d_in[2];
    const float* W_f    = (const float*)d_in[3];
    const float* b_f    = (const float*)d_in[4];
    const float* W_i    = (const float*)d_in[5];
    const float* b_i    = (const float*)d_in[6];
    const float* W_o    = (const float*)d_in[7];
    const float* b_o    = (const float*)d_in[8];
    const float* W_g    = (const float*)d_in[9];
    const float* b_g    = (const float*)d_in[10];
    float* out = (float*)d_out;

    static bool attr_set = false;
    if (!attr_set) {
        cudaFuncSetAttribute(lstm_gemm_kernel,
                             cudaFuncAttributeMaxDynamicSharedMemorySize, SMEM_PIPE);
        attr_set = true;
    }

    convert_a_kernel<<<16384, 256>>>(x_t, h_prev);
    convert_w_kernel<<<256, 256>>>(W_f, W_i, W_o, W_g);
    lstm_gemm_kernel<<<dim3(8, BATCH / MT), 256, SMEM_PIPE>>>(
        c_prev, b_f, b_i, b_o, b_g, out);
}

// round 10
// speedup vs baseline: 1.3674x; 1.3674x over previous
#include <cuda_runtime.h>
#include <cuda_fp16.h>
#include <cstdint>

#define DINLINE __device__ __forceinline__

static constexpr int BATCH = 65536;
static constexpr int HDIM  = 256;
static constexpr int COMB  = 512;
static constexpr int MT    = 128;     // CTA M tile
static constexpr int NT    = 128;     // CTA N tile (= 32 h-cols x 4 gates)
static constexpr int KCH   = 64;      // K chunk
static constexpr int NCHUNK = COMB / KCH;   // 8
static constexpr int NSTAGE = 3;
static constexpr int THREADS = 512;   // 16 warps -> 16 warps/SM at 1 CTA/SM

static constexpr int SA = 72;                       // smem row stride in halves (144B)
static constexpr uint32_t A_TILE_B = MT * SA * 2;   // 18432
static constexpr uint32_t STAGE_B  = 2 * A_TILE_B;  // 36864 (A then W)
static constexpr uint32_t SMEM_PIPE = NSTAGE * STAGE_B;  // 110592 -> 1 CTA/SM (512 thr)
static constexpr int GS = 136;                      // gate smem stride (floats)

// ---- fp16 scratch for packed weights only ----
__device__ __half g_Wp[(size_t)4 * HDIM * COMB];    // packed: row n = hcol*4+gate

// ============================ PTX helpers ============================
DINLINE uint32_t smem_u32(const void* p) {
    uint32_t a;
    asm("{ .reg .u64 t; cvta.to.shared.u64 t, %1; cvt.u32.u64 %0, t; }" : "=r"(a) : "l"(p));
    return a;
}
DINLINE uint32_t h2_as_u32(__half2 h) {
    union { __half2 h; uint32_t u; } c;
    c.h = h;
    return c.u;
}
DINLINE void cp_async16(uint32_t dst, const void* src) {
    asm volatile("cp.async.cg.shared.global [%0], [%1], 16;" :: "r"(dst), "l"(src));
}
DINLINE void cp_commit() { asm volatile("cp.async.commit_group;" ::: "memory"); }
template <int N> DINLINE void cp_wait() {
    asm volatile("cp.async.wait_group %0;" :: "n"(N) : "memory");
}
DINLINE void sts128(uint32_t addr, uint32_t a, uint32_t b, uint32_t c, uint32_t d) {
    asm volatile("st.shared.v4.b32 [%0], {%1, %2, %3, %4};"
                 :: "r"(addr), "r"(a), "r"(b), "r"(c), "r"(d));
}
DINLINE void ldsm_x4(uint32_t (&r)[4], uint32_t addr) {
    asm volatile("ldmatrix.sync.aligned.m8n8.x4.shared.b16 {%0,%1,%2,%3}, [%4];"
                 : "=r"(r[0]), "=r"(r[1]), "=r"(r[2]), "=r"(r[3]) : "r"(addr));
}
DINLINE void mma16816(float (&d)[4], const uint32_t (&a)[4], const uint32_t* b) {
    asm volatile(
        "mma.sync.aligned.m16n8k16.row.col.f32.f16.f16.f32 "
        "{%0,%1,%2,%3}, {%4,%5,%6,%7}, {%8,%9}, {%0,%1,%2,%3};"
        : "+f"(d[0]), "+f"(d[1]), "+f"(d[2]), "+f"(d[3])
        : "r"(a[0]), "r"(a[1]), "r"(a[2]), "r"(a[3]), "r"(b[0]), "r"(b[1]));
}

// ============================ math helpers ============================
DINLINE float fast_sigmoid(float x) { return __fdividef(1.0f, 1.0f + __expf(-x)); }
DINLINE float fast_tanh(float x) {
    float ax = fabsf(x);
    float e  = __expf(-2.0f * ax);
    float r  = __fdividef(1.0f - e, 1.0f + e);
    return copysignf(r, x);
}

// ============================ W prepass ============================
__global__ void __launch_bounds__(256) convert_w_kernel(
    const float* __restrict__ Wf, const float* __restrict__ Wi,
    const float* __restrict__ Wo, const float* __restrict__ Wg) {
    int g  = blockIdx.x * 256 + threadIdx.x;
    int r  = g >> 6;
    int k0 = (g & 63) * 8;
    int gate = r & 3;
    int hcol = r >> 2;
    const float* W = (gate == 0) ? Wf : (gate == 1) ? Wi : (gate == 2) ? Wo : Wg;
    const float* src = W + (size_t)hcol * COMB + k0;
    float4 a = __ldg((const float4*)src);
    float4 b = __ldg((const float4*)src + 1);
    union { uint4 u; __half2 hh2[4]; } pk;
    pk.hh2[0] = __floats2half2_rn(a.x, a.y);
    pk.hh2[1] = __floats2half2_rn(a.z, a.w);
    pk.hh2[2] = __floats2half2_rn(b.x, b.y);
    pk.hh2[3] = __floats2half2_rn(b.z, b.w);
    *reinterpret_cast<uint4*>(g_Wp + (size_t)r * COMB + k0) = pk.u;
}

// ============================ main fused kernel ============================
// grid (8, 512): blockIdx.x = by (32 h-cols), blockIdx.y = M tile.
// 512 threads, 16 warps: warp_m = wid&3 (32 rows), warp_n = wid>>2 (32 cols).

// W stage: cp.async fp16 from packed weights. 1024 tasks / 512 thr = 2 each.
DINLINE void load_w_stage(uint32_t stb, const __half* gW, int kc, int t) {
    #pragma unroll
    for (int i = 0; i < 2; i++) {
        int idx = t + i * 512;
        int n = idx >> 3, c = idx & 7;
        cp_async16(stb + A_TILE_B + (uint32_t)(n * SA + c * 8) * 2,
                   gW + (size_t)n * COMB + kc + c * 8);
    }
}

// A chunk: LDG fp32 (x or h) -> cvt fp16 -> 8 regs. One row-quarter per thread.
DINLINE void load_a_chunk(const float* __restrict__ x, const float* __restrict__ h,
                          int m0, int kc, int t, uint32_t (&st)[8]) {
    const float* src = (kc < 256) ? (x + kc) : (h + (kc - 256));
    int m = t >> 2, q = t & 3;   // row, 16-col quarter
    const float4* p = (const float4*)(src + (size_t)(m0 + m) * 256 + q * 16);
    float4 v0 = __ldg(p + 0);
    float4 v1 = __ldg(p + 1);
    float4 v2 = __ldg(p + 2);
    float4 v3 = __ldg(p + 3);
    st[0] = h2_as_u32(__floats2half2_rn(v0.x, v0.y));
    st[1] = h2_as_u32(__floats2half2_rn(v0.z, v0.w));
    st[2] = h2_as_u32(__floats2half2_rn(v1.x, v1.y));
    st[3] = h2_as_u32(__floats2half2_rn(v1.z, v1.w));
    st[4] = h2_as_u32(__floats2half2_rn(v2.x, v2.y));
    st[5] = h2_as_u32(__floats2half2_rn(v2.z, v2.w));
    st[6] = h2_as_u32(__floats2half2_rn(v3.x, v3.y));
    st[7] = h2_as_u32(__floats2half2_rn(v3.z, v3.w));
}
DINLINE void store_a_chunk(uint32_t stb, int t, const uint32_t (&st)[8]) {
    int m = t >> 2, q = t & 3;
    uint32_t addr = stb + (uint32_t)(m * SA + q * 16) * 2;
    sts128(addr,      st[0], st[1], st[2], st[3]);
    sts128(addr + 16, st[4], st[5], st[6], st[7]);
}

__global__ void __launch_bounds__(THREADS, 1) lstm_gemm_kernel(
    const float* __restrict__ x_t, const float* __restrict__ h_prev,
    const float* __restrict__ c_prev,
    const float* __restrict__ b_f, const float* __restrict__ b_i,
    const float* __restrict__ b_o, const float* __restrict__ b_g,
    float* __restrict__ out) {
    extern __shared__ char smem[];
    const uint32_t sbase = smem_u32(smem);
    float* gsm = (float*)smem;

    const int t    = threadIdx.x;
    const int lane = t & 31;
    const int wid  = t >> 5;
    const int warp_m = wid & 3;          // 4 M-groups (32 rows each)
    const int warp_n = wid >> 2;         // 4 N-groups (32 cols each)
    const int by = blockIdx.x;
    const int m0 = blockIdx.y * MT;

    const __half* gW = g_Wp + (size_t)by * NT * COMB;

    // ldmatrix per-lane address components
    const int A_row = (lane & 7) + ((lane >> 3) & 1) * 8;
    const int A_k   = (lane >> 4) * 8;
    const int B_n   = (lane & 7) + ((lane >> 3) >> 1) * 8;
    const int B_k   = ((lane >> 3) & 1) * 8;

    float acc[2][4][4];                  // 32x32 warp tile
    #pragma unroll
    for (int i = 0; i < 2; i++)
        #pragma unroll
        for (int j = 0; j < 4; j++)
            #pragma unroll
            for (int q = 0; q < 4; q++) acc[i][j][q] = 0.0f;

    // prologue: A chunks 0,1 inline-converted; W chunks 0,1 via cp.async
    {
        uint32_t st[8];
        load_a_chunk(x_t, h_prev, m0, 0, t, st);
        store_a_chunk(sbase + 0 * STAGE_B, t, st);
        load_a_chunk(x_t, h_prev, m0, KCH, t, st);
        store_a_chunk(sbase + 1 * STAGE_B, t, st);
    }
    load_w_stage(sbase + 0 * STAGE_B, gW, 0, t);
    cp_commit();
    load_w_stage(sbase + 1 * STAGE_B, gW, KCH, t);
    cp_commit();

    for (int k = 0; k < NCHUNK; k++) {
        if (k < NCHUNK - 1) cp_wait<1>();
        else                cp_wait<0>();
        __syncthreads();

        const bool pf = (k + 2 < NCHUNK);
        uint32_t st[8];
        if (pf) {
            int sl = (k + 2) % NSTAGE;
            load_a_chunk(x_t, h_prev, m0, (k + 2) * KCH, t, st);  // LDGs fly under mma
            load_w_stage(sbase + sl * STAGE_B, gW, (k + 2) * KCH, t);
            cp_commit();
        }

        const uint32_t stb = sbase + (k % NSTAGE) * STAGE_B;
        #pragma unroll
        for (int ks = 0; ks < 4; ks++) {
            uint32_t af[2][4];
            #pragma unroll
            for (int i = 0; i < 2; i++) {
                uint32_t addr = stb +
                    (uint32_t)((warp_m * 32 + i * 16 + A_row) * SA + ks * 16 + A_k) * 2;
                ldsm_x4(af[i], addr);
            }
            uint32_t bf[4][2];
            #pragma unroll
            for (int jj = 0; jj < 2; jj++) {
                uint32_t r[4];
                uint32_t addr = stb + A_TILE_B +
                    (uint32_t)((warp_n * 32 + jj * 16 + B_n) * SA + ks * 16 + B_k) * 2;
                ldsm_x4(r, addr);
                bf[jj * 2][0] = r[0]; bf[jj * 2][1] = r[1];
                bf[jj * 2 + 1][0] = r[2]; bf[jj * 2 + 1][1] = r[3];
            }
            #pragma unroll
            for (int i = 0; i < 2; i++)
                #pragma unroll
                for (int j = 0; j < 4; j++)
                    mma16816(acc[i][j], af[i], bf[j]);
        }

        if (pf) {
            int sl = (k + 2) % NSTAGE;
            store_a_chunk(sbase + sl * STAGE_B, t, st);
        }
    }

    // ---- stage raw gate values to smem ----
    __syncthreads();
    {
        const int g = lane >> 2, tig = lane & 3;
        #pragma unroll
        for (int i = 0; i < 2; i++) {
            #pragma unroll
            for (int j = 0; j < 4; j++) {
                int r0 = warp_m * 32 + i * 16 + g;
                int n0 = warp_n * 32 + j * 8 + tig * 2;
                *(float2*)(gsm + r0 * GS + n0)       = make_float2(acc[i][j][0], acc[i][j][1]);
                *(float2*)(gsm + (r0 + 8) * GS + n0) = make_float2(acc[i][j][2], acc[i][j][3]);
            }
        }
    }
    __syncthreads();

    // ---- activation epilogue: fully coalesced ----
    const int hc   = t & 31;           // h-col within block
    const int rblk = t >> 5;           // 0..15
    const int hcol = by * 32 + hc;
    const float bF = __ldg(b_f + hcol), bI = __ldg(b_i + hcol);
    const float bO = __ldg(b_o + hcol), bG = __ldg(b_g + hcol);
    const size_t RBH = (size_t)BATCH * HDIM;

    #pragma unroll
    for (int it = 0; it < 8; it++) {
        int row = it * 16 + rblk;
        float4 gv = *(float4*)(gsm + row * GS + hc * 4);  // (f,i,o,g)
        size_t idx = (size_t)(m0 + row) * HDIM + hcol;
        float cp = __ldg(c_prev + idx);
        float f = fast_sigmoid(gv.x + bF);
        float i = fast_sigmoid(gv.y + bI);
        float o = fast_sigmoid(gv.z + bO);
        float g = fast_tanh(gv.w + bG);
        float c = f * cp + i * g;
        float h = o * fast_tanh(c);
        out[idx]           = h;
        out[RBH + idx]     = c;
        out[2 * RBH + idx] = f;
        out[3 * RBH + idx] = i;
        out[4 * RBH + idx] = o;
        out[5 * RBH + idx] = g;
    }
}

// ============================ host launch ============================
extern "C" void kernel_launch(void* const* d_in, const int* in_sizes, int n_in,
                              void* d_out, int out_size) {
    const float* x_t    = (const float*)d_in[0];
    const float* h_prev = (const float*)d_in[1];
    const float* c_prev = (const float*)d_in[2];
    const float* W_f    = (const float*)d_in[3];
    const float* b_f    = (const float*)d_in[4];
    const float* W_i    = (const float*)d_in[5];
    const float* b_i    = (const float*)d_in[6];
    const float* W_o    = (const float*)d_in[7];
    const float* b_o    = (const float*)d_in[8];
    const float* W_g    = (const float*)d_in[9];
    const float* b_g    = (const float*)d_in[10];
    float* out = (float*)d_out;

    static bool attr_set = false;
    if (!attr_set) {
        cudaFuncSetAttribute(lstm_gemm_kernel,
                             cudaFuncAttributeMaxDynamicSharedMemorySize, SMEM_PIPE);
        attr_set = true;
    }

    convert_w_kernel<<<256, 256>>>(W_f, W_i, W_o, W_g);
    lstm_gemm_kernel<<<dim3(8, BATCH / MT), THREADS, SMEM_PIPE>>>(
        x_t, h_prev, c_prev, b_f, b_i, b_o, b_g, out);
}

// round 11
// speedup vs baseline: 2.1660x; 1.5840x over previous
#include <cuda_runtime.h>
#include <cuda_fp16.h>
#include <cstdint>

#define DINLINE __device__ __forceinline__

static constexpr int BATCH = 65536;
static constexpr int HDIM  = 256;
static constexpr int COMB  = 512;
static constexpr int MT    = 128;     // CTA M tile
static constexpr int NT    = 128;     // CTA N tile (= 32 h-cols x 4 gates)
static constexpr int KCH   = 64;      // K chunk
static constexpr int NCHUNK = COMB / KCH;   // 8
static constexpr int NSTAGE = 3;

static constexpr int SA = 72;                       // smem row stride in halves (144B)
static constexpr uint32_t A_TILE_B = MT * SA * 2;   // 18432
static constexpr uint32_t STAGE_B  = 2 * A_TILE_B;  // 36864 (A then W)
static constexpr uint32_t SMEM_PIPE = NSTAGE * STAGE_B;  // 110592 -> 2 CTAs/SM
static constexpr int GS = 136;                      // gate smem stride (floats)

// ---- fp16 scratch (static device arrays; no allocation) ----
__device__ __half g_A16[(size_t)BATCH * COMB];      // concat(x,h) fp16
__device__ __half g_Wp[(size_t)4 * HDIM * COMB];    // packed: row n = hcol*4+gate

// ============================ PTX helpers ============================
DINLINE uint32_t smem_u32(const void* p) {
    uint32_t a;
    asm("{ .reg .u64 t; cvta.to.shared.u64 t, %1; cvt.u32.u64 %0, t; }" : "=r"(a) : "l"(p));
    return a;
}
DINLINE void cp_async16(uint32_t dst, const void* src) {
    asm volatile("cp.async.cg.shared.global [%0], [%1], 16;" :: "r"(dst), "l"(src));
}
DINLINE void cp_commit() { asm volatile("cp.async.commit_group;" ::: "memory"); }
template <int N> DINLINE void cp_wait() {
    asm volatile("cp.async.wait_group %0;" :: "n"(N) : "memory");
}
DINLINE void ldsm_x4(uint32_t (&r)[4], uint32_t addr) {
    asm volatile("ldmatrix.sync.aligned.m8n8.x4.shared.b16 {%0,%1,%2,%3}, [%4];"
                 : "=r"(r[0]), "=r"(r[1]), "=r"(r[2]), "=r"(r[3]) : "r"(addr));
}
DINLINE void mma16816(float (&d)[4], const uint32_t (&a)[4], const uint32_t* b) {
    asm volatile(
        "mma.sync.aligned.m16n8k16.row.col.f32.f16.f16.f32 "
        "{%0,%1,%2,%3}, {%4,%5,%6,%7}, {%8,%9}, {%0,%1,%2,%3};"
        : "+f"(d[0]), "+f"(d[1]), "+f"(d[2]), "+f"(d[3])
        : "r"(a[0]), "r"(a[1]), "r"(a[2]), "r"(a[3]), "r"(b[0]), "r"(b[1]));
}

// ============================ math helpers ============================
DINLINE float fast_sigmoid(float x) { return __fdividef(1.0f, 1.0f + __expf(-x)); }
DINLINE float fast_tanh(float x) {
    float ax = fabsf(x);
    float e  = __expf(-2.0f * ax);
    float r  = __fdividef(1.0f - e, 1.0f + e);
    return copysignf(r, x);
}

// ============================ prepass kernels ============================
__global__ void __launch_bounds__(256) convert_a_kernel(
    const float* __restrict__ x, const float* __restrict__ h) {
    size_t g  = (size_t)blockIdx.x * 256 + threadIdx.x;
    int m  = (int)(g >> 6);
    int k0 = ((int)g & 63) * 8;
    const float* src = (k0 < 256) ? (x + (size_t)m * 256 + k0)
                                  : (h + (size_t)m * 256 + (k0 - 256));
    float4 a = __ldg((const float4*)src);
    float4 b = __ldg((const float4*)src + 1);
    union { uint4 u; __half2 hh[4]; } pk;
    pk.hh[0] = __floats2half2_rn(a.x, a.y);
    pk.hh[1] = __floats2half2_rn(a.z, a.w);
    pk.hh[2] = __floats2half2_rn(b.x, b.y);
    pk.hh[3] = __floats2half2_rn(b.z, b.w);
    *reinterpret_cast<uint4*>(g_A16 + (size_t)m * COMB + k0) = pk.u;
}

__global__ void __launch_bounds__(256) convert_w_kernel(
    const float* __restrict__ Wf, const float* __restrict__ Wi,
    const float* __restrict__ Wo, const float* __restrict__ Wg) {
    int g  = blockIdx.x * 256 + threadIdx.x;
    int r  = g >> 6;
    int k0 = (g & 63) * 8;
    int gate = r & 3;
    int hcol = r >> 2;
    const float* W = (gate == 0) ? Wf : (gate == 1) ? Wi : (gate == 2) ? Wo : Wg;
    const float* src = W + (size_t)hcol * COMB + k0;
    float4 a = __ldg((const float4*)src);
    float4 b = __ldg((const float4*)src + 1);
    union { uint4 u; __half2 hh2[4]; } pk;
    pk.hh2[0] = __floats2half2_rn(a.x, a.y);
    pk.hh2[1] = __floats2half2_rn(a.z, a.w);
    pk.hh2[2] = __floats2half2_rn(b.x, b.y);
    pk.hh2[3] = __floats2half2_rn(b.z, b.w);
    *reinterpret_cast<uint4*>(g_Wp + (size_t)r * COMB + k0) = pk.u;
}

// ============================ main fused GEMM+LSTM kernel ============================
// grid (8, 512): blockIdx.x = by (h-col block of 32), blockIdx.y = M tile.
DINLINE void load_stage(uint32_t stb, const __half* gA, const __half* gW,
                        int kc, int t) {
    #pragma unroll
    for (int i = 0; i < 4; i++) {
        int idx = t + i * 256;           // 0..1023
        int m = idx >> 3, c = idx & 7;
        cp_async16(stb + (uint32_t)(m * SA + c * 8) * 2,
                   gA + (size_t)m * COMB + kc + c * 8);
    }
    #pragma unroll
    for (int i = 0; i < 4; i++) {
        int idx = t + i * 256;
        int n = idx >> 3, c = idx & 7;
        cp_async16(stb + A_TILE_B + (uint32_t)(n * SA + c * 8) * 2,
                   gW + (size_t)n * COMB + kc + c * 8);
    }
}

// fragment load for one ks-step (2 A ldsm + 4 B ldsm)
DINLINE void load_frags(uint32_t stb, int ks,
                        int warp_m, int warp_n,
                        int A_row, int A_k, int B_n, int B_k,
                        uint32_t (&af)[2][4], uint32_t (&bf)[8][2]) {
    #pragma unroll
    for (int i = 0; i < 2; i++) {
        uint32_t addr = stb +
            (uint32_t)((warp_m * 32 + i * 16 + A_row) * SA + ks * 16 + A_k) * 2;
        ldsm_x4(af[i], addr);
    }
    #pragma unroll
    for (int jj = 0; jj < 4; jj++) {
        uint32_t r[4];
        uint32_t addr = stb + A_TILE_B +
            (uint32_t)((warp_n * 64 + jj * 16 + B_n) * SA + ks * 16 + B_k) * 2;
        ldsm_x4(r, addr);
        bf[jj * 2][0] = r[0]; bf[jj * 2][1] = r[1];
        bf[jj * 2 + 1][0] = r[2]; bf[jj * 2 + 1][1] = r[3];
    }
}

__global__ void __launch_bounds__(256, 2) lstm_gemm_kernel(
    const float* __restrict__ c_prev,
    const float* __restrict__ b_f, const float* __restrict__ b_i,
    const float* __restrict__ b_o, const float* __restrict__ b_g,
    float* __restrict__ out) {
    extern __shared__ char smem[];
    const uint32_t sbase = smem_u32(smem);
    float* gsm = (float*)smem;

    const int t    = threadIdx.x;
    const int lane = t & 31;
    const int wid  = t >> 5;
    const int warp_m = wid & 3;          // 4 M-warps (32 rows each)
    const int warp_n = wid >> 2;         // 2 N-warps (64 cols each)
    const int by = blockIdx.x;
    const int m0 = blockIdx.y * MT;

    const __half* gA = g_A16 + (size_t)m0 * COMB;
    const __half* gW = g_Wp + (size_t)by * NT * COMB;

    const int A_row = (lane & 7) + ((lane >> 3) & 1) * 8;
    const int A_k   = (lane >> 4) * 8;
    const int B_n   = (lane & 7) + ((lane >> 3) >> 1) * 8;
    const int B_k   = ((lane >> 3) & 1) * 8;

    float acc[2][8][4];
    #pragma unroll
    for (int i = 0; i < 2; i++)
        #pragma unroll
        for (int j = 0; j < 8; j++)
            #pragma unroll
            for (int q = 0; q < 4; q++) acc[i][j][q] = 0.0f;

    #pragma unroll
    for (int s = 0; s < 2; s++) {
        load_stage(sbase + s * STAGE_B, gA, gW, s * KCH, t);
        cp_commit();
    }

    #pragma unroll
    for (int k = 0; k < NCHUNK; k++) {
        if (k < NCHUNK - 1) cp_wait<1>();
        else                cp_wait<0>();
        __syncthreads();

        if (k + 2 < NCHUNK) {
            load_stage(sbase + ((k + 2) % NSTAGE) * STAGE_B, gA, gW,
                       (k + 2) * KCH, t);
            cp_commit();
        }

        const uint32_t stb = sbase + (k % NSTAGE) * STAGE_B;
        // ks-level software pipeline with static double buffers
        uint32_t af[2][2][4];
        uint32_t bf[2][8][2];
        load_frags(stb, 0, warp_m, warp_n, A_row, A_k, B_n, B_k, af[0], bf[0]);
        #pragma unroll
        for (int ks = 0; ks < 4; ks++) {
            const int cur = ks & 1;
            if (ks < 3)
                load_frags(stb, ks + 1, warp_m, warp_n, A_row, A_k, B_n, B_k,
                           af[cur ^ 1], bf[cur ^ 1]);
            #pragma unroll
            for (int i = 0; i < 2; i++)
                #pragma unroll
                for (int j = 0; j < 8; j++)
                    mma16816(acc[i][j], af[cur][i], bf[cur][j]);
        }
    }

    // ---- prefetch c_prev for the epilogue (hide DRAM latency under staging) ----
    const int hc   = t & 31;
    const int rblk = t >> 5;
    const int hcol = by * 32 + hc;
    const size_t RBH = (size_t)BATCH * HDIM;
    float cpre[16];
    #pragma unroll
    for (int it = 0; it < 16; it++) {
        int row = it * 8 + rblk;
        cpre[it] = __ldg(c_prev + (size_t)(m0 + row) * HDIM + hcol);
    }

    // ---- stage raw gate values to smem ----
    __syncthreads();
    {
        const int g = lane >> 2, tig = lane & 3;
        #pragma unroll
        for (int i = 0; i < 2; i++) {
            #pragma unroll
            for (int j = 0; j < 8; j++) {
                int r0 = warp_m * 32 + i * 16 + g;
                int n0 = warp_n * 64 + j * 8 + tig * 2;
                *(float2*)(gsm + r0 * GS + n0)       = make_float2(acc[i][j][0], acc[i][j][1]);
                *(float2*)(gsm + (r0 + 8) * GS + n0) = make_float2(acc[i][j][2], acc[i][j][3]);
            }
        }
    }
    __syncthreads();

    // ---- activation epilogue: fully coalesced ----
    const float bF = __ldg(b_f + hcol), bI = __ldg(b_i + hcol);
    const float bO = __ldg(b_o + hcol), bG = __ldg(b_g + hcol);

    #pragma unroll
    for (int it = 0; it < 16; it++) {
        int row = it * 8 + rblk;
        float4 gv = *(float4*)(gsm + row * GS + hc * 4);  // (f,i,o,g)
        size_t idx = (size_t)(m0 + row) * HDIM + hcol;
        float f = fast_sigmoid(gv.x + bF);
        float i = fast_sigmoid(gv.y + bI);
        float o = fast_sigmoid(gv.z + bO);
        float g = fast_tanh(gv.w + bG);
        float c = f * cpre[it] + i * g;
        float h = o * fast_tanh(c);
        out[idx]           = h;
        out[RBH + idx]     = c;
        out[2 * RBH + idx] = f;
        out[3 * RBH + idx] = i;
        out[4 * RBH + idx] = o;
        out[5 * RBH + idx] = g;
    }
}

// ============================ host launch ============================
extern "C" void kernel_launch(void* const* d_in, const int* in_sizes, int n_in,
                              void* d_out, int out_size) {
    const float* x_t    = (const float*)d_in[0];
    const float* h_prev = (const float*)d_in[1];
    const float* c_prev = (const float*)d_in[2];
    const float* W_f    = (const float*)d_in[3];
    const float* b_f    = (const float*)d_in[4];
    const float* W_i    = (const float*)d_in[5];
    const float* b_i    = (const float*)d_in[6];
    const float* W_o    = (const float*)d_in[7];
    const float* b_o    = (const float*)d_in[8];
    const float* W_g    = (const float*)d_in[9];
    const float* b_g    = (const float*)d_in[10];
    float* out = (float*)d_out;

    static bool attr_set = false;
    if (!attr_set) {
        cudaFuncSetAttribute(lstm_gemm_kernel,
                             cudaFuncAttributeMaxDynamicSharedMemorySize, SMEM_PIPE);
        attr_set = true;
    }

    convert_a_kernel<<<16384, 256>>>(x_t, h_prev);
    convert_w_kernel<<<256, 256>>>(W_f, W_i, W_o, W_g);
    lstm_gemm_kernel<<<dim3(8, BATCH / MT), 256, SMEM_PIPE>>>(
        c_prev, b_f, b_i, b_o, b_g, out);
}